// round 9
// baseline (speedup 1.0000x reference)
#include <cuda_runtime.h>
#include <cuda_fp16.h>
#include <cstdint>

typedef unsigned int u32;

#define BB   512
#define TT   1024
#define TM1  1023
#define II   32
#define EE   32
#define HH   256
#define KIN  64

#define NCTA 32
#define BPB  16
#define NTH  512     // 16 warps

#define TILES_W01 172
#define TILES_W   156
#define NTILE_TOT (2*TILES_W01 + 14*TILES_W)   // 2528

#define XSTR  328    // XB row stride (halfs): [x(64) | h0(256)]
#define HSTR  264    // H1B row stride (halfs)
#define HMSTR 260    // h-master row stride (floats)

// dynamic SMEM layout (bytes)
#define O_XB   0
#define O_H1B  10496                    // 16*328*2
#define O_YF   18944                    // + 16*264*2
#define O_H0M  20992                    // + 16*32*4
#define O_H1M  37632                    // + 16*260*4
#define O_BS   54272                    // + 16*260*4
#define O_BOU  62464                    // + 8*256*4
#define SMEMB  62720

// fragment schedule: tile = 512B = 32 lanes x 8 halfs (a0..a3 order) -- same as R8
__device__ __align__(1024) __half SCHED[NTILE_TOT * 256];

__global__ void prep_kernel(const float* __restrict__ wih0, const float* __restrict__ whh0,
                            const float* __restrict__ wih1, const float* __restrict__ whh1,
                            const float* __restrict__ wout)
{
    int idx = blockIdx.x * blockDim.x + threadIdx.x;
    if (idx >= NTILE_TOT * 256) return;
    const int j    = idx & 7;
    const int lane = (idx >> 3) & 31;
    const int tile = idx >> 8;

    int w, r;
    if (tile < 2 * TILES_W01) { w = tile / TILES_W01; r = tile % TILES_W01; }
    else { w = 2 + (tile - 2 * TILES_W01) / TILES_W; r = (tile - 2 * TILES_W01) % TILES_W; }

    const int g  = lane >> 2;
    const int tq = lane & 3;
    const int il = g + 8 * ((j >> 1) & 1);
    const int kl = tq * 2 + (j & 1) + 8 * (j >> 2);

    float v;
    if (r < 60) {              // G0: per kt {r,z,in|hn}
        const int kt = r / 3, kind = r % 3;
        const int row = kind * 256 + 16 * w + il;
        if (kt < 4) v = wih0[row * KIN + kt * 16 + kl];
        else        v = whh0[row * HH + (kt - 4) * 16 + kl];
    } else if (r < 108) {      // GB: Whh1 {r,z,hn}
        const int rr = r - 60, kt = rr / 3, kind = rr % 3;
        v = whh1[(kind * 256 + 16 * w + il) * HH + kt * 16 + kl];
    } else if (r < 156) {      // GC: Wih1 {r,z,in}
        const int rr = r - 108, kt = rr / 3, kind = rr % 3;
        v = wih1[(kind * 256 + 16 * w + il) * HH + kt * 16 + kl];
    } else {                   // GY: wout (warps 0,1)
        const int kt = r - 156;
        v = wout[(16 * w + il) * HH + kt * 16 + kl];
    }
    SCHED[tile * 256 + lane * 8 + j] = __float2half_rn(v);
}

__device__ __forceinline__ float tanha(float x) {
    float y; asm("tanh.approx.f32 %0, %1;" : "=f"(y) : "f"(x)); return y;
}
__device__ __forceinline__ float siga(float x) {
    return fmaf(tanha(0.5f * x), 0.5f, 0.5f);
}
__device__ __forceinline__ void hmma(float* c, uint4 a, u32 b0, u32 b1) {
    asm volatile("mma.sync.aligned.m16n8k16.row.col.f32.f16.f16.f32 "
                 "{%0,%1,%2,%3}, {%4,%5,%6,%7}, {%8,%9}, {%0,%1,%2,%3};"
                 : "+f"(c[0]), "+f"(c[1]), "+f"(c[2]), "+f"(c[3])
                 : "r"(a.x), "r"(a.y), "r"(a.z), "r"(a.w), "r"(b0), "r"(b1));
}

__global__ void __launch_bounds__(NTH, 1)
arrnn_kernel(const float* __restrict__ X,
             const float* __restrict__ ENC,
             const int*   __restrict__ MASK,
             const float* __restrict__ bih0, const float* __restrict__ bhh0,
             const float* __restrict__ bih1, const float* __restrict__ bhh1,
             const float* __restrict__ bout,
             float* __restrict__ outseq, float* __restrict__ outh1,
             int write_h1)
{
    extern __shared__ __align__(16) char dyn[];
    __half* XB  = (__half*)(dyn + O_XB);    // [16][XSTR]
    __half* H1B = (__half*)(dyn + O_H1B);   // [16][HSTR]
    float*  yf  = (float*)(dyn + O_YF);     // [16][32]
    float*  h0m = (float*)(dyn + O_H0M);    // [16][HMSTR] fp32 masters
    float*  h1m = (float*)(dyn + O_H1M);
    float*  bsm = (float*)(dyn + O_BS);     // [8][256] biases
    float*  bou = (float*)(dyn + O_BOU);    // [32]

    const int tid  = threadIdx.x;
    const int wid  = tid >> 5;
    const int lane = tid & 31;
    const int g    = lane >> 2;
    const int tq   = lane & 3;
    const int b0g  = blockIdx.x * BPB;

    const int u1 = 16 * wid + g;
    const int u2 = u1 + 8;

    // ---- init ----
    for (int i = tid; i < BPB * XSTR; i += NTH) XB[i] = __float2half_rn(0.f);
    for (int i = tid; i < BPB * HSTR; i += NTH) H1B[i] = __float2half_rn(0.f);
    for (int i = tid; i < BPB * II; i += NTH) yf[i] = 0.f;
    for (int i = tid; i < BPB * HMSTR; i += NTH) { h0m[i] = 0.f; h1m[i] = 0.f; }
    for (int i = tid; i < 8 * 256; i += NTH) {
        const int k = i >> 8, u = i & 255;
        float v;
        switch (k) {
            case 0: v = bih0[u] + bhh0[u]; break;
            case 1: v = bih0[256 + u] + bhh0[256 + u]; break;
            case 2: v = bih0[512 + u]; break;
            case 3: v = bhh0[512 + u]; break;
            case 4: v = bih1[u] + bhh1[u]; break;
            case 5: v = bih1[256 + u] + bhh1[256 + u]; break;
            case 6: v = bih1[512 + u]; break;
            default: v = bhh1[512 + u]; break;
        }
        bsm[i] = v;
    }
    if (tid < II) bou[tid] = bout[tid];
    __syncthreads();

    const __half* tpw = SCHED +
        (size_t)((wid < 2) ? wid * TILES_W01 : 2 * TILES_W01 + (wid - 2) * TILES_W) * 256
        + lane * 8;

    for (int t = 0; t < TM1; ++t) {
        // ---- Phase A: build x into XB[:, 0:64] ----
        for (int i = tid; i < BPB * KIN; i += NTH) {
            const int b = i >> 6, k = i & 63;
            const int gb = b0g + b;
            float v;
            if (k < II) {
                const bool keep = (t == 0) || (MASK[gb * TT + t] != 0);
                v = keep ? X[((size_t)gb * TT + t) * II + k] : yf[b * II + k];
            } else {
                v = ENC[((size_t)gb * TT + (t + 1)) * EE + (k - II)];
            }
            XB[b * XSTR + k] = __float2half_rn(v);
        }
        __syncthreads();   // bar1: XB complete

        const __half* tp = tpw;
        const __half* xr0 = XB + g * XSTR;
        const __half* xr1 = XB + (g + 8) * XSTR;

        // ---- G0: layer0 gates over [x|h0old], k=320, 2 N-tiles ----
        float Cr[8] = {0,0,0,0,0,0,0,0}, Cz[8] = {0,0,0,0,0,0,0,0};
        float Ci[8] = {0,0,0,0,0,0,0,0}, Ch[8] = {0,0,0,0,0,0,0,0};
#pragma unroll
        for (int kt = 0; kt < 4; ++kt) {
            const u32 b00 = *(const u32*)(xr0 + kt * 16 + 2 * tq);
            const u32 b01 = *(const u32*)(xr0 + kt * 16 + 8 + 2 * tq);
            const u32 b10 = *(const u32*)(xr1 + kt * 16 + 2 * tq);
            const u32 b11 = *(const u32*)(xr1 + kt * 16 + 8 + 2 * tq);
            uint4 ar = *(const uint4*)tp; tp += 256;
            uint4 az = *(const uint4*)tp; tp += 256;
            uint4 ai = *(const uint4*)tp; tp += 256;
            hmma(Cr, ar, b00, b01); hmma(Cr + 4, ar, b10, b11);
            hmma(Cz, az, b00, b01); hmma(Cz + 4, az, b10, b11);
            hmma(Ci, ai, b00, b01); hmma(Ci + 4, ai, b10, b11);
        }
#pragma unroll 4
        for (int kt = 4; kt < 20; ++kt) {
            const u32 b00 = *(const u32*)(xr0 + kt * 16 + 2 * tq);
            const u32 b01 = *(const u32*)(xr0 + kt * 16 + 8 + 2 * tq);
            const u32 b10 = *(const u32*)(xr1 + kt * 16 + 2 * tq);
            const u32 b11 = *(const u32*)(xr1 + kt * 16 + 8 + 2 * tq);
            uint4 ar = *(const uint4*)tp; tp += 256;
            uint4 az = *(const uint4*)tp; tp += 256;
            uint4 ah = *(const uint4*)tp; tp += 256;
            hmma(Cr, ar, b00, b01); hmma(Cr + 4, ar, b10, b11);
            hmma(Cz, az, b00, b01); hmma(Cz + 4, az, b10, b11);
            hmma(Ch, ah, b00, b01); hmma(Ch + 4, ah, b10, b11);
        }

        // ---- GB: Whh1 x h1old ----
        float Dr[8] = {0,0,0,0,0,0,0,0}, Dz[8] = {0,0,0,0,0,0,0,0}, Dh[8] = {0,0,0,0,0,0,0,0};
        {
            const __half* hr0 = H1B + g * HSTR;
            const __half* hr1 = H1B + (g + 8) * HSTR;
#pragma unroll 4
            for (int kt = 0; kt < 16; ++kt) {
                const u32 b00 = *(const u32*)(hr0 + kt * 16 + 2 * tq);
                const u32 b01 = *(const u32*)(hr0 + kt * 16 + 8 + 2 * tq);
                const u32 b10 = *(const u32*)(hr1 + kt * 16 + 2 * tq);
                const u32 b11 = *(const u32*)(hr1 + kt * 16 + 8 + 2 * tq);
                uint4 ar = *(const uint4*)tp; tp += 256;
                uint4 az = *(const uint4*)tp; tp += 256;
                uint4 ah = *(const uint4*)tp; tp += 256;
                hmma(Dr, ar, b00, b01); hmma(Dr + 4, ar, b10, b11);
                hmma(Dz, az, b00, b01); hmma(Dz + 4, az, b10, b11);
                hmma(Dh, ah, b00, b01); hmma(Dh + 4, ah, b10, b11);
            }
        }
        __syncthreads();   // bar2: G0/GB reads of XB,H1B done

        // ---- epi0 -> h0new (fp32 master) + fp16 into XB[:,64:] ----
        {
            const float br_a = bsm[u1],       br_b = bsm[u2];
            const float bz_a = bsm[256 + u1], bz_b = bsm[256 + u2];
            const float bi_a = bsm[512 + u1], bi_b = bsm[512 + u2];
            const float bn_a = bsm[768 + u1], bn_b = bsm[768 + u2];
#pragma unroll
            for (int nt = 0; nt < 2; ++nt)
#pragma unroll
                for (int p = 0; p < 4; ++p) {
                    const bool aa = (p < 2);
                    const int unit = aa ? u1 : u2;
                    const int b = 8 * nt + 2 * tq + (p & 1);
                    const int ix = nt * 4 + p;
                    const float r = siga(Cr[ix] + (aa ? br_a : br_b));
                    const float z = siga(Cz[ix] + (aa ? bz_a : bz_b));
                    const float n = tanha(Ci[ix] + (aa ? bi_a : bi_b)
                                          + r * (Ch[ix] + (aa ? bn_a : bn_b)));
                    float h = h0m[b * HMSTR + unit];
                    h = (1.0f - z) * n + z * h;
                    h0m[b * HMSTR + unit] = h;
                    XB[b * XSTR + 64 + unit] = __float2half_rn(h);
                }
        }
        __syncthreads();   // bar3: h0new visible

        // ---- GC: Wih1 x h0new ----
        float Di[8] = {0,0,0,0,0,0,0,0};
        {
            const __half* hx0 = XB + g * XSTR + 64;
            const __half* hx1 = XB + (g + 8) * XSTR + 64;
#pragma unroll 4
            for (int kt = 0; kt < 16; ++kt) {
                const u32 b00 = *(const u32*)(hx0 + kt * 16 + 2 * tq);
                const u32 b01 = *(const u32*)(hx0 + kt * 16 + 8 + 2 * tq);
                const u32 b10 = *(const u32*)(hx1 + kt * 16 + 2 * tq);
                const u32 b11 = *(const u32*)(hx1 + kt * 16 + 8 + 2 * tq);
                uint4 ar = *(const uint4*)tp; tp += 256;
                uint4 az = *(const uint4*)tp; tp += 256;
                uint4 ai = *(const uint4*)tp; tp += 256;
                hmma(Dr, ar, b00, b01); hmma(Dr + 4, ar, b10, b11);
                hmma(Dz, az, b00, b01); hmma(Dz + 4, az, b10, b11);
                hmma(Di, ai, b00, b01); hmma(Di + 4, ai, b10, b11);
            }
        }

        // ---- epi1 -> h1new ----
        {
            const float br_a = bsm[1024 + u1], br_b = bsm[1024 + u2];
            const float bz_a = bsm[1280 + u1], bz_b = bsm[1280 + u2];
            const float bi_a = bsm[1536 + u1], bi_b = bsm[1536 + u2];
            const float bn_a = bsm[1792 + u1], bn_b = bsm[1792 + u2];
#pragma unroll
            for (int nt = 0; nt < 2; ++nt)
#pragma unroll
                for (int p = 0; p < 4; ++p) {
                    const bool aa = (p < 2);
                    const int unit = aa ? u1 : u2;
                    const int b = 8 * nt + 2 * tq + (p & 1);
                    const int ix = nt * 4 + p;
                    const float r = siga(Dr[ix] + (aa ? br_a : br_b));
                    const float z = siga(Dz[ix] + (aa ? bz_a : bz_b));
                    const float n = tanha(Di[ix] + (aa ? bi_a : bi_b)
                                          + r * (Dh[ix] + (aa ? bn_a : bn_b)));
                    float h = h1m[b * HMSTR + unit];
                    h = (1.0f - z) * n + z * h;
                    h1m[b * HMSTR + unit] = h;
                    H1B[b * HSTR + unit] = __float2half_rn(h);
                }
        }
        __syncthreads();   // bar4: h1new visible

        // ---- GY: readout (warps 0,1) ----
        if (wid < 2) {
            float Y[8] = {0,0,0,0,0,0,0,0};
            const __half* hr0 = H1B + g * HSTR;
            const __half* hr1 = H1B + (g + 8) * HSTR;
#pragma unroll 4
            for (int kt = 0; kt < 16; ++kt) {
                const u32 b00 = *(const u32*)(hr0 + kt * 16 + 2 * tq);
                const u32 b01 = *(const u32*)(hr0 + kt * 16 + 8 + 2 * tq);
                const u32 b10 = *(const u32*)(hr1 + kt * 16 + 2 * tq);
                const u32 b11 = *(const u32*)(hr1 + kt * 16 + 8 + 2 * tq);
                uint4 ay = *(const uint4*)tp; tp += 256;
                hmma(Y, ay, b00, b01); hmma(Y + 4, ay, b10, b11);
            }
            const float by_a = bou[16 * wid + g];
            const float by_b = bou[16 * wid + g + 8];
#pragma unroll
            for (int nt = 0; nt < 2; ++nt)
#pragma unroll
                for (int p = 0; p < 4; ++p) {
                    const bool aa = (p < 2);
                    const int i = 16 * wid + g + (aa ? 0 : 8);
                    const int b = 8 * nt + 2 * tq + (p & 1);
                    const float y = Y[nt * 4 + p] + (aa ? by_a : by_b);
                    yf[b * II + i] = y;
                    outseq[((size_t)(b0g + b) * TM1 + t) * II + i] = y;
                }
        }
        __syncthreads();   // bar5: yf ready
    }

    if (write_h1) {
        for (int i = tid; i < BPB * HH; i += NTH) {
            const int b = i >> 8, u = i & 255;
            outh1[(size_t)(b0g + b) * HH + u] = h1m[b * HMSTR + u];
        }
    }
}

extern "C" void kernel_launch(void* const* d_in, const int* in_sizes, int n_in,
                              void* d_out, int out_size) {
    const float* X    = (const float*)d_in[0];
    const float* ENC  = (const float*)d_in[1];
    const int*   MASK = (const int*)d_in[2];
    const float* wih0 = (const float*)d_in[3];
    const float* whh0 = (const float*)d_in[4];
    const float* bih0 = (const float*)d_in[5];
    const float* bhh0 = (const float*)d_in[6];
    const float* wih1 = (const float*)d_in[7];
    const float* whh1 = (const float*)d_in[8];
    const float* bih1 = (const float*)d_in[9];
    const float* bhh1 = (const float*)d_in[10];
    const float* wout = (const float*)d_in[11];
    const float* bout = (const float*)d_in[12];

    float* outseq = (float*)d_out;
    const int seqsz = BB * TM1 * II;
    float* outh1  = outseq + seqsz;
    const int write_h1 = (out_size >= seqsz + BB * HH) ? 1 : 0;

    prep_kernel<<<(NTILE_TOT * 256 + 255) / 256, 256>>>(wih0, whh0, wih1, whh1, wout);

    cudaFuncSetAttribute(arrnn_kernel, cudaFuncAttributeMaxDynamicSharedMemorySize, SMEMB);
    arrnn_kernel<<<NCTA, NTH, SMEMB>>>(X, ENC, MASK,
                                       bih0, bhh0, bih1, bhh1, bout,
                                       outseq, outh1, write_h1);
}

// round 10
// speedup vs baseline: 1.1548x; 1.1548x over previous
#include <cuda_runtime.h>
#include <cuda_fp16.h>
#include <cstdint>

typedef unsigned int u32;

#define BB   512
#define TT   1024
#define TM1  1023
#define II   32
#define EE   32
#define HH   256
#define KIN  64

#define NCTA 64
#define BPB  8
#define NTH  512     // 16 warps

#define TILES_W01 172
#define TILES_W   156
#define NTILE_TOT (2*TILES_W01 + 14*TILES_W)   // 2528
#define XSTR 328
#define HSTR 264

#define RES_T  27                 // resident tiles per warp (G0 kt0-8)
#define RES_B  (RES_T * 512)      // bytes per warp

// dynamic SMEM layout (bytes)
#define O_XB   0                              // 8*328*2 = 5248
#define O_H1B  5248                           // 8*264*2 = 4224
#define O_YF   9472                           // 8*32*4  = 1024
#define O_RES  10496                          // 16*27*512 = 221184
#define SMEMB  (10496 + 16 * RES_B)           // 231680

// fragment schedule: tile = 512B = 32 lanes x 8 halfs -- identical to R8
__device__ __align__(1024) __half SCHED[NTILE_TOT * 256];

__global__ void prep_kernel(const float* __restrict__ wih0, const float* __restrict__ whh0,
                            const float* __restrict__ wih1, const float* __restrict__ whh1,
                            const float* __restrict__ wout)
{
    int idx = blockIdx.x * blockDim.x + threadIdx.x;
    if (idx >= NTILE_TOT * 256) return;
    const int j    = idx & 7;
    const int lane = (idx >> 3) & 31;
    const int tile = idx >> 8;

    int w, r;
    if (tile < 2 * TILES_W01) { w = tile / TILES_W01; r = tile % TILES_W01; }
    else { w = 2 + (tile - 2 * TILES_W01) / TILES_W; r = (tile - 2 * TILES_W01) % TILES_W; }

    const int g  = lane >> 2;
    const int tq = lane & 3;
    const int il = g + 8 * ((j >> 1) & 1);
    const int kl = tq * 2 + (j & 1) + 8 * (j >> 2);

    float v;
    if (r < 60) {              // G0: per kt {r,z,in|hn}
        const int kt = r / 3, kind = r % 3;
        const int row = kind * 256 + 16 * w + il;
        if (kt < 4) v = wih0[row * KIN + kt * 16 + kl];
        else        v = whh0[row * HH + (kt - 4) * 16 + kl];
    } else if (r < 108) {      // GB: Whh1 {r,z,hn}
        const int rr = r - 60, kt = rr / 3, kind = rr % 3;
        v = whh1[(kind * 256 + 16 * w + il) * HH + kt * 16 + kl];
    } else if (r < 156) {      // GC: Wih1 {r,z,in}
        const int rr = r - 108, kt = rr / 3, kind = rr % 3;
        v = wih1[(kind * 256 + 16 * w + il) * HH + kt * 16 + kl];
    } else {                   // GY: wout (warps 0,1)
        const int kt = r - 156;
        v = wout[(16 * w + il) * HH + kt * 16 + kl];
    }
    SCHED[tile * 256 + lane * 8 + j] = __float2half_rn(v);
}

__device__ __forceinline__ float tanha(float x) {
    float y; asm("tanh.approx.f32 %0, %1;" : "=f"(y) : "f"(x)); return y;
}
__device__ __forceinline__ float siga(float x) {
    return fmaf(tanha(0.5f * x), 0.5f, 0.5f);
}
__device__ __forceinline__ void hmma(float* c, uint4 a, u32 b0, u32 b1) {
    asm volatile("mma.sync.aligned.m16n8k16.row.col.f32.f16.f16.f32 "
                 "{%0,%1,%2,%3}, {%4,%5,%6,%7}, {%8,%9}, {%0,%1,%2,%3};"
                 : "+f"(c[0]), "+f"(c[1]), "+f"(c[2]), "+f"(c[3])
                 : "r"(a.x), "r"(a.y), "r"(a.z), "r"(a.w), "r"(b0), "r"(b1));
}

__global__ void __launch_bounds__(NTH, 1)
arrnn_kernel(const float* __restrict__ X,
             const float* __restrict__ ENC,
             const int*   __restrict__ MASK,
             const float* __restrict__ bih0, const float* __restrict__ bhh0,
             const float* __restrict__ bih1, const float* __restrict__ bhh1,
             const float* __restrict__ bout,
             float* __restrict__ outseq, float* __restrict__ outh1,
             int write_h1)
{
    extern __shared__ __align__(16) char dyn[];
    __half* XB  = (__half*)(dyn + O_XB);    // [8][XSTR]: [x(64) | h0(256)]
    __half* H1B = (__half*)(dyn + O_H1B);   // [8][HSTR]
    float*  yf  = (float*)(dyn + O_YF);     // [8][32]

    const int tid  = threadIdx.x;
    const int wid  = tid >> 5;
    const int lane = tid & 31;
    const int g    = lane >> 2;
    const int tq   = lane & 3;
    const int b0g  = blockIdx.x * BPB;

    const int u1 = 16 * wid + g;
    const int u2 = u1 + 8;

    const float br0a = bih0[u1] + bhh0[u1],             br0b = bih0[u2] + bhh0[u2];
    const float bz0a = bih0[u1 + 256] + bhh0[u1 + 256], bz0b = bih0[u2 + 256] + bhh0[u2 + 256];
    const float bi0a = bih0[u1 + 512],                  bi0b = bih0[u2 + 512];
    const float bn0a = bhh0[u1 + 512],                  bn0b = bhh0[u2 + 512];
    const float br1a = bih1[u1] + bhh1[u1],             br1b = bih1[u2] + bhh1[u2];
    const float bz1a = bih1[u1 + 256] + bhh1[u1 + 256], bz1b = bih1[u2 + 256] + bhh1[u2 + 256];
    const float bi1a = bih1[u1 + 512],                  bi1b = bih1[u2 + 512];
    const float bn1a = bhh1[u1 + 512],                  bn1b = bhh1[u2 + 512];
    const float bya  = (wid < 2) ? bout[16 * wid + g] : 0.0f;
    const float byb  = (wid < 2) ? bout[16 * wid + g + 8] : 0.0f;

    float h0[4] = {0.f, 0.f, 0.f, 0.f};
    float h1[4] = {0.f, 0.f, 0.f, 0.f};

    for (int i = tid; i < BPB * XSTR; i += NTH) XB[i] = __float2half_rn(0.f);
    for (int i = tid; i < BPB * HSTR; i += NTH) H1B[i] = __float2half_rn(0.f);
    for (int i = tid; i < BPB * II; i += NTH) yf[i] = 0.f;

    const __half* tpw = SCHED +
        (size_t)((wid < 2) ? wid * TILES_W01 : 2 * TILES_W01 + (wid - 2) * TILES_W) * 256
        + lane * 8;

    // copy resident tiles (G0 kt0-8) into SMEM, per warp
    char* rbase = dyn + O_RES + wid * RES_B + lane * 16;
#pragma unroll
    for (int i = 0; i < RES_T; ++i)
        *(uint4*)(rbase + i * 512) = *(const uint4*)(tpw + i * 256);
    __syncthreads();

    const __half* tpw_ldg = tpw + RES_T * 256;   // LDG stream starts after resident tiles

    const int bb = tid >> 6;
    const int kk = tid & 63;

    for (int t = 0; t < TM1; ++t) {
        // ---- Phase A: build x into XB[:, 0:64] ----
        {
            const int gb = b0g + bb;
            float v;
            if (kk < II) {
                const bool keep = (t == 0) || (MASK[gb * TT + t] != 0);
                v = keep ? X[((size_t)gb * TT + t) * II + kk] : yf[bb * II + kk];
            } else {
                v = ENC[((size_t)gb * TT + (t + 1)) * EE + (kk - II)];
            }
            XB[bb * XSTR + kk] = __float2half_rn(v);
        }
        __syncthreads();   // bar1

        const __half* tp = tpw_ldg;
        const __half* xr = XB + g * XSTR;

        // ---- G0: layer0 gates over [x|h0old], k=320 ----
        float Cr[4] = {0.f,0.f,0.f,0.f}, Cz[4] = {0.f,0.f,0.f,0.f};
        float Ci[4] = {0.f,0.f,0.f,0.f}, Ch[4] = {0.f,0.f,0.f,0.f};
#pragma unroll
        for (int kt = 0; kt < 4; ++kt) {     // resident: r,z,i
            const u32 b0 = *(const u32*)(xr + kt * 16 + 2 * tq);
            const u32 b1 = *(const u32*)(xr + kt * 16 + 8 + 2 * tq);
            const uint4 ar = *(const uint4*)(rbase + (3 * kt    ) * 512);
            const uint4 az = *(const uint4*)(rbase + (3 * kt + 1) * 512);
            const uint4 ai = *(const uint4*)(rbase + (3 * kt + 2) * 512);
            hmma(Cr, ar, b0, b1); hmma(Cz, az, b0, b1); hmma(Ci, ai, b0, b1);
        }
#pragma unroll
        for (int kt = 4; kt < 9; ++kt) {     // resident: r,z,h
            const u32 b0 = *(const u32*)(xr + kt * 16 + 2 * tq);
            const u32 b1 = *(const u32*)(xr + kt * 16 + 8 + 2 * tq);
            const uint4 ar = *(const uint4*)(rbase + (12 + 3 * (kt - 4)    ) * 512);
            const uint4 az = *(const uint4*)(rbase + (12 + 3 * (kt - 4) + 1) * 512);
            const uint4 ah = *(const uint4*)(rbase + (12 + 3 * (kt - 4) + 2) * 512);
            hmma(Cr, ar, b0, b1); hmma(Cz, az, b0, b1); hmma(Ch, ah, b0, b1);
        }
#pragma unroll 4
        for (int kt = 9; kt < 20; ++kt) {    // streamed: r,z,h
            const u32 b0 = *(const u32*)(xr + kt * 16 + 2 * tq);
            const u32 b1 = *(const u32*)(xr + kt * 16 + 8 + 2 * tq);
            uint4 ar = *(const uint4*)tp; tp += 256;
            uint4 az = *(const uint4*)tp; tp += 256;
            uint4 ah = *(const uint4*)tp; tp += 256;
            hmma(Cr, ar, b0, b1); hmma(Cz, az, b0, b1); hmma(Ch, ah, b0, b1);
        }

        // ---- GB: Whh1 x h1old ----
        float Dr[4] = {0.f,0.f,0.f,0.f}, Dz[4] = {0.f,0.f,0.f,0.f}, Dh[4] = {0.f,0.f,0.f,0.f};
        {
            const __half* hr = H1B + g * HSTR;
#pragma unroll 4
            for (int kt = 0; kt < 16; ++kt) {
                const u32 b0 = *(const u32*)(hr + kt * 16 + 2 * tq);
                const u32 b1 = *(const u32*)(hr + kt * 16 + 8 + 2 * tq);
                uint4 ar = *(const uint4*)tp; tp += 256;
                uint4 az = *(const uint4*)tp; tp += 256;
                uint4 ah = *(const uint4*)tp; tp += 256;
                hmma(Dr, ar, b0, b1); hmma(Dz, az, b0, b1); hmma(Dh, ah, b0, b1);
            }
        }
        __syncthreads();   // bar2

        // ---- epi0 -> h0new fp16 into XB[:,64:] ----
#pragma unroll
        for (int p = 0; p < 4; ++p) {
            const bool a = (p < 2);
            const float rr = siga(Cr[p] + (a ? br0a : br0b));
            const float zz = siga(Cz[p] + (a ? bz0a : bz0b));
            const float nn = tanha(Ci[p] + (a ? bi0a : bi0b) + rr * (Ch[p] + (a ? bn0a : bn0b)));
            h0[p] = (1.0f - zz) * nn + zz * h0[p];
            XB[(2 * tq + (p & 1)) * XSTR + 64 + (a ? u1 : u2)] = __float2half_rn(h0[p]);
        }
        __syncthreads();   // bar3

        // ---- GC: Wih1 x h0new ----
        float Di[4] = {0.f,0.f,0.f,0.f};
        {
            const __half* hx = XB + g * XSTR + 64;
#pragma unroll 4
            for (int kt = 0; kt < 16; ++kt) {
                const u32 b0 = *(const u32*)(hx + kt * 16 + 2 * tq);
                const u32 b1 = *(const u32*)(hx + kt * 16 + 8 + 2 * tq);
                uint4 ar = *(const uint4*)tp; tp += 256;
                uint4 az = *(const uint4*)tp; tp += 256;
                uint4 ai = *(const uint4*)tp; tp += 256;
                hmma(Dr, ar, b0, b1); hmma(Dz, az, b0, b1); hmma(Di, ai, b0, b1);
            }
        }

        // ---- epi1 -> h1new ----
#pragma unroll
        for (int p = 0; p < 4; ++p) {
            const bool a = (p < 2);
            const float rr = siga(Dr[p] + (a ? br1a : br1b));
            const float zz = siga(Dz[p] + (a ? bz1a : bz1b));
            const float nn = tanha(Di[p] + (a ? bi1a : bi1b) + rr * (Dh[p] + (a ? bn1a : bn1b)));
            h1[p] = (1.0f - zz) * nn + zz * h1[p];
            H1B[(2 * tq + (p & 1)) * HSTR + (a ? u1 : u2)] = __float2half_rn(h1[p]);
        }
        __syncthreads();   // bar4

        // ---- GY: readout (warps 0,1) ----
        if (wid < 2) {
            float Y[4] = {0.f,0.f,0.f,0.f};
            const __half* hr = H1B + g * HSTR;
#pragma unroll 4
            for (int kt = 0; kt < 16; ++kt) {
                const u32 b0 = *(const u32*)(hr + kt * 16 + 2 * tq);
                const u32 b1 = *(const u32*)(hr + kt * 16 + 8 + 2 * tq);
                uint4 ay = *(const uint4*)tp; tp += 256;
                hmma(Y, ay, b0, b1);
            }
#pragma unroll
            for (int p = 0; p < 4; ++p) {
                const bool a = (p < 2);
                const int i = 16 * wid + g + (a ? 0 : 8);
                const int b = 2 * tq + (p & 1);
                const float y = Y[p] + (a ? bya : byb);
                yf[b * II + i] = y;
                outseq[((size_t)(b0g + b) * TM1 + t) * II + i] = y;
            }
        }
        __syncthreads();   // bar5
    }

    if (write_h1) {
#pragma unroll
        for (int p = 0; p < 4; ++p) {
            const int b = b0g + 2 * tq + (p & 1);
            const int u = (p < 2) ? u1 : u2;
            outh1[(size_t)b * HH + u] = h1[p];
        }
    }
}

extern "C" void kernel_launch(void* const* d_in, const int* in_sizes, int n_in,
                              void* d_out, int out_size) {
    const float* X    = (const float*)d_in[0];
    const float* ENC  = (const float*)d_in[1];
    const int*   MASK = (const int*)d_in[2];
    const float* wih0 = (const float*)d_in[3];
    const float* whh0 = (const float*)d_in[4];
    const float* bih0 = (const float*)d_in[5];
    const float* bhh0 = (const float*)d_in[6];
    const float* wih1 = (const float*)d_in[7];
    const float* whh1 = (const float*)d_in[8];
    const float* bih1 = (const float*)d_in[9];
    const float* bhh1 = (const float*)d_in[10];
    const float* wout = (const float*)d_in[11];
    const float* bout = (const float*)d_in[12];

    float* outseq = (float*)d_out;
    const int seqsz = BB * TM1 * II;
    float* outh1  = outseq + seqsz;
    const int write_h1 = (out_size >= seqsz + BB * HH) ? 1 : 0;

    prep_kernel<<<(NTILE_TOT * 256 + 255) / 256, 256>>>(wih0, whh0, wih1, whh1, wout);

    cudaFuncSetAttribute(arrnn_kernel, cudaFuncAttributeMaxDynamicSharedMemorySize, SMEMB);
    arrnn_kernel<<<NCTA, NTH, SMEMB>>>(X, ENC, MASK,
                                       bih0, bhh0, bih1, bhh1, bout,
                                       outseq, outh1, write_h1);
}

// round 11
// speedup vs baseline: 1.3969x; 1.2096x over previous
#include <cuda_runtime.h>
#include <cuda_fp16.h>
#include <cstdint>

typedef unsigned int u32;

#define BB   512
#define TT   1024
#define TM1  1023
#define II   32
#define EE   32
#define HH   256
#define KIN  64

#define NCTA 64
#define BPB  8
#define NTH  512     // 16 warps

#define TILES_W01 172
#define TILES_W   156
#define NTILE_TOT (2*TILES_W01 + 14*TILES_W)   // 2528

// XB row: [x(64) | h0_buf0(256) | h0_buf1(256)] pad-> 584 halfs (292 words = 4 mod 32)
#define XSTR 584
#define HSTR 264

// fragment schedule: tile = 512B = 32 lanes x 8 halfs -- identical layout to R8
__device__ __align__(1024) __half SCHED[NTILE_TOT * 256];

__global__ void prep_kernel(const float* __restrict__ wih0, const float* __restrict__ whh0,
                            const float* __restrict__ wih1, const float* __restrict__ whh1,
                            const float* __restrict__ wout)
{
    int idx = blockIdx.x * blockDim.x + threadIdx.x;
    if (idx >= NTILE_TOT * 256) return;
    const int j    = idx & 7;
    const int lane = (idx >> 3) & 31;
    const int tile = idx >> 8;

    int w, r;
    if (tile < 2 * TILES_W01) { w = tile / TILES_W01; r = tile % TILES_W01; }
    else { w = 2 + (tile - 2 * TILES_W01) / TILES_W; r = (tile - 2 * TILES_W01) % TILES_W; }

    const int g  = lane >> 2;
    const int tq = lane & 3;
    const int il = g + 8 * ((j >> 1) & 1);
    const int kl = tq * 2 + (j & 1) + 8 * (j >> 2);

    float v;
    if (r < 60) {              // G0: per kt {r,z,in|hn}
        const int kt = r / 3, kind = r % 3;
        const int row = kind * 256 + 16 * w + il;
        if (kt < 4) v = wih0[row * KIN + kt * 16 + kl];
        else        v = whh0[row * HH + (kt - 4) * 16 + kl];
    } else if (r < 108) {      // GB: Whh1 {r,z,hn}
        const int rr = r - 60, kt = rr / 3, kind = rr % 3;
        v = whh1[(kind * 256 + 16 * w + il) * HH + kt * 16 + kl];
    } else if (r < 156) {      // GC: Wih1 {r,z,in}
        const int rr = r - 108, kt = rr / 3, kind = rr % 3;
        v = wih1[(kind * 256 + 16 * w + il) * HH + kt * 16 + kl];
    } else {                   // GY: wout (warps 0,1)
        const int kt = r - 156;
        v = wout[(16 * w + il) * HH + kt * 16 + kl];
    }
    SCHED[tile * 256 + lane * 8 + j] = __float2half_rn(v);
}

__device__ __forceinline__ float tanha(float x) {
    float y; asm("tanh.approx.f32 %0, %1;" : "=f"(y) : "f"(x)); return y;
}
__device__ __forceinline__ float siga(float x) {
    return fmaf(tanha(0.5f * x), 0.5f, 0.5f);
}
__device__ __forceinline__ void hmma(float* c, uint4 a, u32 b0, u32 b1) {
    asm volatile("mma.sync.aligned.m16n8k16.row.col.f32.f16.f16.f32 "
                 "{%0,%1,%2,%3}, {%4,%5,%6,%7}, {%8,%9}, {%0,%1,%2,%3};"
                 : "+f"(c[0]), "+f"(c[1]), "+f"(c[2]), "+f"(c[3])
                 : "r"(a.x), "r"(a.y), "r"(a.z), "r"(a.w), "r"(b0), "r"(b1));
}

__global__ void __launch_bounds__(NTH, 1)
arrnn_kernel(const float* __restrict__ X,
             const float* __restrict__ ENC,
             const int*   __restrict__ MASK,
             const float* __restrict__ bih0, const float* __restrict__ bhh0,
             const float* __restrict__ bih1, const float* __restrict__ bhh1,
             const float* __restrict__ bout,
             float* __restrict__ outseq, float* __restrict__ outh1,
             int write_h1)
{
    __shared__ __align__(16) __half XB[BPB * XSTR];
    __shared__ __align__(16) __half H1B[BPB * HSTR];
    __shared__ __align__(16) float  bsm[8 * 256];

    const int tid  = threadIdx.x;
    const int wid  = tid >> 5;
    const int lane = tid & 31;
    const int g    = lane >> 2;
    const int tq   = lane & 3;
    const int b0g  = blockIdx.x * BPB;

    const int u1 = 16 * wid + g;
    const int u2 = u1 + 8;

    // biases in SMEM (frees registers)
    for (int i = tid; i < 8 * 256; i += NTH) {
        const int k = i >> 8, u = i & 255;
        float v;
        switch (k) {
            case 0: v = bih0[u] + bhh0[u]; break;
            case 1: v = bih0[256 + u] + bhh0[256 + u]; break;
            case 2: v = bih0[512 + u]; break;
            case 3: v = bhh0[512 + u]; break;
            case 4: v = bih1[u] + bhh1[u]; break;
            case 5: v = bih1[256 + u] + bhh1[256 + u]; break;
            case 6: v = bih1[512 + u]; break;
            default: v = bhh1[512 + u]; break;
        }
        bsm[i] = v;
    }
    const float bya = (wid < 2) ? bout[16 * wid + g] : 0.0f;
    const float byb = (wid < 2) ? bout[16 * wid + g + 8] : 0.0f;

    float h0[4] = {0.f, 0.f, 0.f, 0.f};
    float h1[4] = {0.f, 0.f, 0.f, 0.f};

    // init: zero h0 buffers + H1B, build x/enc for t=0
    for (int i = tid; i < BPB * 512; i += NTH)
        XB[(i >> 9) * XSTR + 64 + (i & 511)] = __float2half_rn(0.f);
    for (int i = tid; i < BPB * HSTR; i += NTH) H1B[i] = __float2half_rn(0.f);
    for (int i = tid; i < BPB * KIN; i += NTH) {
        const int b = i >> 6, k = i & 63;
        const int gb = b0g + b;
        const float v = (k < II) ? X[((size_t)gb * TT) * II + k]
                                 : ENC[((size_t)gb * TT + 1) * EE + (k - II)];
        XB[b * XSTR + k] = __float2half_rn(v);
    }
    __syncthreads();

    const __half* tpw = SCHED +
        (size_t)((wid < 2) ? wid * TILES_W01 : 2 * TILES_W01 + (wid - 2) * TILES_W) * 256
        + lane * 8;

    // prefetch G0 kt0 fragments for t=0
    uint4 pg0 = *(const uint4*)(tpw);
    uint4 pg1 = *(const uint4*)(tpw + 256);
    uint4 pg2 = *(const uint4*)(tpw + 512);

    for (int t = 0; t < TM1; ++t) {
        const int rp = t & 1;        // h0 read buffer
        const int wp = rp ^ 1;       // h0 write buffer
        const __half* xr  = XB + g * XSTR;
        const __half* hr0 = xr + 64 + rp * 256;

        // ================= G0: layer0 gates, k=320 =================
        float Cr[4] = {0.f,0.f,0.f,0.f}, Cz[4] = {0.f,0.f,0.f,0.f};
        float Ci[4] = {0.f,0.f,0.f,0.f}, Ch[4] = {0.f,0.f,0.f,0.f};
        {   // kt0 from prefetch
            const u32 b0 = *(const u32*)(xr + 2 * tq);
            const u32 b1 = *(const u32*)(xr + 8 + 2 * tq);
            hmma(Cr, pg0, b0, b1); hmma(Cz, pg1, b0, b1); hmma(Ci, pg2, b0, b1);
        }
        const __half* tp = tpw + 3 * 256;
#pragma unroll
        for (int kt = 1; kt < 4; ++kt) {
            const u32 b0 = *(const u32*)(xr + kt * 16 + 2 * tq);
            const u32 b1 = *(const u32*)(xr + kt * 16 + 8 + 2 * tq);
            uint4 ar = *(const uint4*)tp; tp += 256;
            uint4 az = *(const uint4*)tp; tp += 256;
            uint4 ai = *(const uint4*)tp; tp += 256;
            hmma(Cr, ar, b0, b1); hmma(Cz, az, b0, b1); hmma(Ci, ai, b0, b1);
        }
#pragma unroll 4
        for (int kt = 0; kt < 16; ++kt) {
            const u32 b0 = *(const u32*)(hr0 + kt * 16 + 2 * tq);
            const u32 b1 = *(const u32*)(hr0 + kt * 16 + 8 + 2 * tq);
            uint4 ar = *(const uint4*)tp; tp += 256;
            uint4 az = *(const uint4*)tp; tp += 256;
            uint4 ah = *(const uint4*)tp; tp += 256;
            hmma(Cr, ar, b0, b1); hmma(Cz, az, b0, b1); hmma(Ch, ah, b0, b1);
        }

        // ================= GB: Whh1 x h1_old =================
        float Dr[4] = {0.f,0.f,0.f,0.f}, Dz[4] = {0.f,0.f,0.f,0.f}, Dh[4] = {0.f,0.f,0.f,0.f};
        {
            const __half* hr = H1B + g * HSTR;
#pragma unroll 4
            for (int kt = 0; kt < 16; ++kt) {
                const u32 b0 = *(const u32*)(hr + kt * 16 + 2 * tq);
                const u32 b1 = *(const u32*)(hr + kt * 16 + 8 + 2 * tq);
                uint4 ar = *(const uint4*)tp; tp += 256;
                uint4 az = *(const uint4*)tp; tp += 256;
                uint4 ah = *(const uint4*)tp; tp += 256;
                hmma(Dr, ar, b0, b1); hmma(Dz, az, b0, b1); hmma(Dh, ah, b0, b1);
            }
        }

        // prefetch GC kt0 (before bar3)
        uint4 pc0 = *(const uint4*)(tp);
        uint4 pc1 = *(const uint4*)(tp + 256);
        uint4 pc2 = *(const uint4*)(tp + 512);
        tp += 3 * 256;

        // ---- epi0 (no barrier needed: writes h0 buf wp, G0 read buf rp) ----
        {
            const float br_a = bsm[u1],       br_b = bsm[u2];
            const float bz_a = bsm[256 + u1], bz_b = bsm[256 + u2];
            const float bi_a = bsm[512 + u1], bi_b = bsm[512 + u2];
            const float bn_a = bsm[768 + u1], bn_b = bsm[768 + u2];
#pragma unroll
            for (int p = 0; p < 4; ++p) {
                const bool a = (p < 2);
                const float rr = siga(Cr[p] + (a ? br_a : br_b));
                const float zz = siga(Cz[p] + (a ? bz_a : bz_b));
                const float nn = tanha(Ci[p] + (a ? bi_a : bi_b) + rr * (Ch[p] + (a ? bn_a : bn_b)));
                h0[p] = (1.0f - zz) * nn + zz * h0[p];
                XB[(2 * tq + (p & 1)) * XSTR + 64 + wp * 256 + (a ? u1 : u2)]
                    = __float2half_rn(h0[p]);
            }
        }
        __syncthreads();   // BAR-A: h0_new published; all G0/GB reads complete

        // enc columns for step t+1 (warps 2-9; disjoint from GC reads)
        if (wid >= 2 && wid < 10) {
            const int i2 = tid - 64;
            const int b = i2 >> 5, k = i2 & 31;
            const int eidx = (t + 2 < TT) ? (t + 2) : (TT - 1);
            XB[b * XSTR + 32 + k] =
                __float2half_rn(ENC[((size_t)(b0g + b) * TT + eidx) * EE + k]);
        }

        // ================= GC: Wih1 x h0_new =================
        float Di[4] = {0.f,0.f,0.f,0.f};
        {
            const __half* hw = XB + g * XSTR + 64 + wp * 256;
            {   // kt0 from prefetch
                const u32 b0 = *(const u32*)(hw + 2 * tq);
                const u32 b1 = *(const u32*)(hw + 8 + 2 * tq);
                hmma(Dr, pc0, b0, b1); hmma(Dz, pc1, b0, b1); hmma(Di, pc2, b0, b1);
            }
#pragma unroll 4
            for (int kt = 1; kt < 16; ++kt) {
                const u32 b0 = *(const u32*)(hw + kt * 16 + 2 * tq);
                const u32 b1 = *(const u32*)(hw + kt * 16 + 8 + 2 * tq);
                uint4 ar = *(const uint4*)tp; tp += 256;
                uint4 az = *(const uint4*)tp; tp += 256;
                uint4 ai = *(const uint4*)tp; tp += 256;
                hmma(Dr, ar, b0, b1); hmma(Dz, az, b0, b1); hmma(Di, ai, b0, b1);
            }
        }

        // ---- epi1 (no barrier: all GB reads of H1B finished before BAR-A) ----
        {
            const float br_a = bsm[1024 + u1], br_b = bsm[1024 + u2];
            const float bz_a = bsm[1280 + u1], bz_b = bsm[1280 + u2];
            const float bi_a = bsm[1536 + u1], bi_b = bsm[1536 + u2];
            const float bn_a = bsm[1792 + u1], bn_b = bsm[1792 + u2];
#pragma unroll
            for (int p = 0; p < 4; ++p) {
                const bool a = (p < 2);
                const float rr = siga(Dr[p] + (a ? br_a : br_b));
                const float zz = siga(Dz[p] + (a ? bz_a : bz_b));
                const float nn = tanha(Di[p] + (a ? bi_a : bi_b) + rr * (Dh[p] + (a ? bn_a : bn_b)));
                h1[p] = (1.0f - zz) * nn + zz * h1[p];
                H1B[(2 * tq + (p & 1)) * HSTR + (a ? u1 : u2)] = __float2half_rn(h1[p]);
            }
        }

        // warps 0,1: prefetch GY kt0 + next-step mask/X (before BAR-B)
        uint4 py0;
        int kp0 = 0, kp1 = 0;
        float xpre[4];
        if (wid < 2) {
            py0 = *(const uint4*)tp;
            kp0 = MASK[(b0g + 2 * tq) * TT + (t + 1)];
            kp1 = MASK[(b0g + 2 * tq + 1) * TT + (t + 1)];
#pragma unroll
            for (int p = 0; p < 4; ++p) {
                const int i = 16 * wid + g + ((p < 2) ? 0 : 8);
                const int b = 2 * tq + (p & 1);
                xpre[p] = X[((size_t)(b0g + b) * TT + (t + 1)) * II + i];
            }
        }
        __syncthreads();   // BAR-B: h1_new published

        // ================= GY + next-step x build (warps 0,1) =================
        if (wid < 2) {
            float Y[4] = {0.f,0.f,0.f,0.f};
            const __half* hr = H1B + g * HSTR;
            {   // kt0 from prefetch
                const u32 b0 = *(const u32*)(hr + 2 * tq);
                const u32 b1 = *(const u32*)(hr + 8 + 2 * tq);
                hmma(Y, py0, b0, b1);
            }
            tp += 256;
#pragma unroll 4
            for (int kt = 1; kt < 16; ++kt) {
                const u32 b0 = *(const u32*)(hr + kt * 16 + 2 * tq);
                const u32 b1 = *(const u32*)(hr + kt * 16 + 8 + 2 * tq);
                uint4 ay = *(const uint4*)tp; tp += 256;
                hmma(Y, ay, b0, b1);
            }
#pragma unroll
            for (int p = 0; p < 4; ++p) {
                const bool a = (p < 2);
                const int i = 16 * wid + g + (a ? 0 : 8);
                const int b = 2 * tq + (p & 1);
                const float y = Y[p] + (a ? bya : byb);
                outseq[((size_t)(b0g + b) * TM1 + t) * II + i] = y;
                const bool keep = ((p & 1) ? kp1 : kp0) != 0;
                XB[b * XSTR + i] = __float2half_rn(keep ? xpre[p] : y);
            }
        }

        // all warps: prefetch next-step G0 kt0
        pg0 = *(const uint4*)(tpw);
        pg1 = *(const uint4*)(tpw + 256);
        pg2 = *(const uint4*)(tpw + 512);
        __syncthreads();   // BAR-C: x/y columns published
    }

    if (write_h1) {
#pragma unroll
        for (int p = 0; p < 4; ++p) {
            const int b = b0g + 2 * tq + (p & 1);
            const int u = (p < 2) ? u1 : u2;
            outh1[(size_t)b * HH + u] = h1[p];
        }
    }
}

extern "C" void kernel_launch(void* const* d_in, const int* in_sizes, int n_in,
                              void* d_out, int out_size) {
    const float* X    = (const float*)d_in[0];
    const float* ENC  = (const float*)d_in[1];
    const int*   MASK = (const int*)d_in[2];
    const float* wih0 = (const float*)d_in[3];
    const float* whh0 = (const float*)d_in[4];
    const float* bih0 = (const float*)d_in[5];
    const float* bhh0 = (const float*)d_in[6];
    const float* wih1 = (const float*)d_in[7];
    const float* whh1 = (const float*)d_in[8];
    const float* bih1 = (const float*)d_in[9];
    const float* bhh1 = (const float*)d_in[10];
    const float* wout = (const float*)d_in[11];
    const float* bout = (const float*)d_in[12];

    float* outseq = (float*)d_out;
    const int seqsz = BB * TM1 * II;
    float* outh1  = outseq + seqsz;
    const int write_h1 = (out_size >= seqsz + BB * HH) ? 1 : 0;

    prep_kernel<<<(NTILE_TOT * 256 + 255) / 256, 256>>>(wih0, whh0, wih1, whh1, wout);

    arrnn_kernel<<<NCTA, NTH>>>(X, ENC, MASK,
                                bih0, bhh0, bih1, bhh1, bout,
                                outseq, outh1, write_h1);
}

// round 13
// speedup vs baseline: 1.5237x; 1.0907x over previous
#include <cuda_runtime.h>
#include <cuda_fp16.h>
#include <cstdint>

typedef unsigned int u32;

#define BB   512
#define TT   1024
#define TM1  1023
#define II   32
#define EE   32
#define HH   256
#define KIN  64

#define NCTA 64
#define BPB  8
#define NTH  512     // 16 warps

// per-warp streams: warps 0-7: 156 tiles; warps 8-15: 160 (incl. 4 GY tiles)
#define NTILE_TOT (8*156 + 8*160)   // 2528

// XB row: [x(64) | h0_buf0(256) | h0_buf1(256)] pad-> 584 halfs
#define XSTR 584
#define HSTR 264

__device__ __align__(1024) __half SCHED[NTILE_TOT * 256];

// ---- prep: consumption order = head(x-part 12) | GC(48) | G0h(48) | GB(48) | [GY(4) w>=8]
__global__ void prep_kernel(const float* __restrict__ wih0, const float* __restrict__ whh0,
                            const float* __restrict__ wih1, const float* __restrict__ whh1,
                            const float* __restrict__ wout)
{
    int idx = blockIdx.x * blockDim.x + threadIdx.x;
    if (idx >= NTILE_TOT * 256) return;
    const int j    = idx & 7;
    const int lane = (idx >> 3) & 31;
    const int tile = idx >> 8;

    int w, r;
    if (tile < 8 * 156) { w = tile / 156; r = tile % 156; }
    else { int t2 = tile - 8 * 156; w = 8 + t2 / 160; r = t2 % 160; }

    const int tq = lane & 3;
    const int il = (lane >> 2) + 8 * ((j >> 1) & 1);
    const int kl = tq * 2 + (j & 1) + 8 * (j >> 2);

    float v;
    if (r < 12) {              // head: W_ih0 x-part, kt0-3 {r,z,i}
        const int kt = r / 3, kind = r % 3;
        v = wih0[(kind * 256 + 16 * w + il) * KIN + kt * 16 + kl];
    } else if (r < 60) {       // GC: W_ih1 {r,z,i}
        const int rr = r - 12, kt = rr / 3, kind = rr % 3;
        v = wih1[(kind * 256 + 16 * w + il) * HH + kt * 16 + kl];
    } else if (r < 108) {      // G0h: W_hh0 {r,z,h}
        const int rr = r - 60, kt = rr / 3, kind = rr % 3;
        v = whh0[(kind * 256 + 16 * w + il) * HH + kt * 16 + kl];
    } else if (r < 156) {      // GB: W_hh1 {r,z,h}
        const int rr = r - 108, kt = rr / 3, kind = rr % 3;
        v = whh1[(kind * 256 + 16 * w + il) * HH + kt * 16 + kl];
    } else {                   // GY (warps 8-15): kt = 2*(w-8)+(local>>1), mtile = local&1
        const int local = r - 156;
        const int kt = 2 * (w - 8) + (local >> 1);
        const int mt = local & 1;
        v = wout[(16 * mt + il) * HH + kt * 16 + kl];
    }
    SCHED[tile * 256 + lane * 8 + j] = __float2half_rn(v);
}

__device__ __forceinline__ float tanha(float x) {
    float y; asm("tanh.approx.f32 %0, %1;" : "=f"(y) : "f"(x)); return y;
}
__device__ __forceinline__ float siga(float x) {
    return fmaf(tanha(0.5f * x), 0.5f, 0.5f);
}
__device__ __forceinline__ void hmma(float* c, uint4 a, u32 b0, u32 b1) {
    asm volatile("mma.sync.aligned.m16n8k16.row.col.f32.f16.f16.f32 "
                 "{%0,%1,%2,%3}, {%4,%5,%6,%7}, {%8,%9}, {%0,%1,%2,%3};"
                 : "+f"(c[0]), "+f"(c[1]), "+f"(c[2]), "+f"(c[3])
                 : "r"(a.x), "r"(a.y), "r"(a.z), "r"(a.w), "r"(b0), "r"(b1));
}

__global__ void __launch_bounds__(NTH, 1)
arrnn_kernel(const float* __restrict__ X,
             const float* __restrict__ ENC,
             const int*   __restrict__ MASK,
             const float* __restrict__ bih0, const float* __restrict__ bhh0,
             const float* __restrict__ bih1, const float* __restrict__ bhh1,
             const float* __restrict__ bout,
             float* __restrict__ outseq, float* __restrict__ outh1,
             int write_h1)
{
    __shared__ __align__(16) __half XB[BPB * XSTR];
    __shared__ __align__(16) __half H1B[BPB * HSTR];
    __shared__ __align__(16) float  bsm[8 * 256];
    __shared__ __align__(16) float4 PY[16][32];    // GY partials [w8*2+mtile][lane]

    const int tid  = threadIdx.x;
    const int wid  = tid >> 5;
    const int lane = tid & 31;
    const int g    = lane >> 2;
    const int tq   = lane & 3;
    const int b0g  = blockIdx.x * BPB;

    const int u1 = 16 * wid + g;
    const int u2 = u1 + 8;

    for (int i = tid; i < 8 * 256; i += NTH) {
        const int k = i >> 8, u = i & 255;
        float v;
        switch (k) {
            case 0: v = bih0[u] + bhh0[u]; break;
            case 1: v = bih0[256 + u] + bhh0[256 + u]; break;
            case 2: v = bih0[512 + u]; break;
            case 3: v = bhh0[512 + u]; break;
            case 4: v = bih1[u] + bhh1[u]; break;
            case 5: v = bih1[256 + u] + bhh1[256 + u]; break;
            case 6: v = bih1[512 + u]; break;
            default: v = bhh1[512 + u]; break;
        }
        bsm[i] = v;
    }
    const float bya = (wid < 2) ? bout[16 * wid + g] : 0.0f;
    const float byb = (wid < 2) ? bout[16 * wid + g + 8] : 0.0f;

    float h0[4] = {0.f, 0.f, 0.f, 0.f};
    float h1[4] = {0.f, 0.f, 0.f, 0.f};

    // carry accumulators (h-parts of next step), zero = correct for t=0
    float Cr[4] = {0,0,0,0}, Cz[4] = {0,0,0,0}, Ch[4] = {0,0,0,0};
    float Dr[4] = {0,0,0,0}, Dz[4] = {0,0,0,0}, Dh[4] = {0,0,0,0};

    // init XB / H1B, build x(0)|enc(1)
    for (int i = tid; i < BPB * 512; i += NTH)
        XB[(i >> 9) * XSTR + 64 + (i & 511)] = __float2half_rn(0.f);
    for (int i = tid; i < BPB * HSTR; i += NTH) H1B[i] = __float2half_rn(0.f);
    for (int i = tid; i < BPB * KIN; i += NTH) {
        const int b = i >> 6, k = i & 63;
        const int gb = b0g + b;
        const float v = (k < II) ? X[((size_t)gb * TT) * II + k]
                                 : ENC[((size_t)gb * TT + 1) * EE + (k - II)];
        XB[b * XSTR + k] = __float2half_rn(v);
    }
    __syncthreads();

    const int base_t = (wid < 8) ? wid * 156 : 8 * 156 + (wid - 8) * 160;
    const __half* tpw = SCHED + (size_t)base_t * 256 + lane * 8;
    const __half* gyp = tpw + 156 * 256;     // valid for wid>=8 only

    // prefetch head kt0 (tiles 0-2)
    uint4 pg0 = *(const uint4*)(tpw);
    uint4 pg1 = *(const uint4*)(tpw + 256);
    uint4 pg2 = *(const uint4*)(tpw + 512);

    for (int t = 0; t < TM1; ++t) {
        const int bi = t & 1;                 // h0 buffer for this step
        const __half* xr = XB + g * XSTR;

        // ================= HEAD: x-part of G0 (kt0-3) =================
        float Ci[4] = {0.f,0.f,0.f,0.f};
        {
            const u32 b0 = *(const u32*)(xr + 2 * tq);
            const u32 b1 = *(const u32*)(xr + 8 + 2 * tq);
            hmma(Cr, pg0, b0, b1); hmma(Cz, pg1, b0, b1); hmma(Ci, pg2, b0, b1);
        }
        const __half* tp = tpw + 3 * 256;
#pragma unroll
        for (int kt = 1; kt < 4; ++kt) {
            const u32 b0 = *(const u32*)(xr + kt * 16 + 2 * tq);
            const u32 b1 = *(const u32*)(xr + kt * 16 + 8 + 2 * tq);
            uint4 ar = *(const uint4*)tp; tp += 256;
            uint4 az = *(const uint4*)tp; tp += 256;
            uint4 ai = *(const uint4*)tp; tp += 256;
            hmma(Cr, ar, b0, b1); hmma(Cz, az, b0, b1); hmma(Ci, ai, b0, b1);
        }
        // prefetch GC kt0 (tiles 12-14)
        uint4 pc0 = *(const uint4*)(tp);
        uint4 pc1 = *(const uint4*)(tp + 256);
        uint4 pc2 = *(const uint4*)(tp + 512);
        tp += 3 * 256;

        // ---- epi0: h0(t) -> XB buf bi ----
        {
            const float br_a = bsm[u1],       br_b = bsm[u2];
            const float bz_a = bsm[256 + u1], bz_b = bsm[256 + u2];
            const float bi_a = bsm[512 + u1], bi_b = bsm[512 + u2];
            const float bn_a = bsm[768 + u1], bn_b = bsm[768 + u2];
#pragma unroll
            for (int p = 0; p < 4; ++p) {
                const bool a = (p < 2);
                const float rr = siga(Cr[p] + (a ? br_a : br_b));
                const float zz = siga(Cz[p] + (a ? bz_a : bz_b));
                const float nn = tanha(Ci[p] + (a ? bi_a : bi_b) + rr * (Ch[p] + (a ? bn_a : bn_b)));
                h0[p] = (1.0f - zz) * nn + zz * h0[p];
                XB[(2 * tq + (p & 1)) * XSTR + 64 + bi * 256 + (a ? u1 : u2)]
                    = __float2half_rn(h0[p]);
            }
        }
        __syncthreads();   // BAR-A: h0(t) published

        // ================= GC: Wih1 x h0(t), 16kt =================
        float Di[4] = {0.f,0.f,0.f,0.f};
        {
            const __half* hb = XB + g * XSTR + 64 + bi * 256;
            {
                const u32 b0 = *(const u32*)(hb + 2 * tq);
                const u32 b1 = *(const u32*)(hb + 8 + 2 * tq);
                hmma(Dr, pc0, b0, b1); hmma(Dz, pc1, b0, b1); hmma(Di, pc2, b0, b1);
            }
#pragma unroll 4
            for (int kt = 1; kt < 16; ++kt) {
                const u32 b0 = *(const u32*)(hb + kt * 16 + 2 * tq);
                const u32 b1 = *(const u32*)(hb + kt * 16 + 8 + 2 * tq);
                uint4 ar = *(const uint4*)tp; tp += 256;
                uint4 az = *(const uint4*)tp; tp += 256;
                uint4 ai = *(const uint4*)tp; tp += 256;
                hmma(Dr, ar, b0, b1); hmma(Dz, az, b0, b1); hmma(Di, ai, b0, b1);
            }
        }

        // ---- epi1: h1(t) -> H1B ----
        {
            const float br_a = bsm[1024 + u1], br_b = bsm[1024 + u2];
            const float bz_a = bsm[1280 + u1], bz_b = bsm[1280 + u2];
            const float bi_a = bsm[1536 + u1], bi_b = bsm[1536 + u2];
            const float bn_a = bsm[1792 + u1], bn_b = bsm[1792 + u2];
#pragma unroll
            for (int p = 0; p < 4; ++p) {
                const bool a = (p < 2);
                const float rr = siga(Dr[p] + (a ? br_a : br_b));
                const float zz = siga(Dz[p] + (a ? bz_a : bz_b));
                const float nn = tanha(Di[p] + (a ? bi_a : bi_b) + rr * (Dh[p] + (a ? bn_a : bn_b)));
                h1[p] = (1.0f - zz) * nn + zz * h1[p];
                H1B[(2 * tq + (p & 1)) * HSTR + (a ? u1 : u2)] = __float2half_rn(h1[p]);
            }
        }

        // prefetch tail kt0 (tiles 60-62) + warps 0,1: next-step mask/X
        pg0 = *(const uint4*)(tpw + 60 * 256);
        pg1 = *(const uint4*)(tpw + 61 * 256);
        pg2 = *(const uint4*)(tpw + 62 * 256);
        tp += 3 * 256;     // FIX (R12 bug): skip prefetched tiles 60-62 in the stream
        int kp0 = 0, kp1 = 0;
        float xpre[4];
        if (wid < 2) {
            kp0 = MASK[(b0g + 2 * tq) * TT + (t + 1)];
            kp1 = MASK[(b0g + 2 * tq + 1) * TT + (t + 1)];
#pragma unroll
            for (int p = 0; p < 4; ++p) {
                const int i = 16 * wid + g + ((p < 2) ? 0 : 8);
                const int b = 2 * tq + (p & 1);
                xpre[p] = X[((size_t)(b0g + b) * TT + (t + 1)) * II + i];
            }
        }
        __syncthreads();   // BAR-B: h1(t) published

        // ================= TAIL =================
        // enc(t+2) for the next head (warps 2-9)
        if (wid >= 2 && wid < 10) {
            const int i2 = tid - 64;
            const int b = i2 >> 5, k = i2 & 31;
            const int eidx = (t + 2 < TT) ? (t + 2) : (TT - 1);
            XB[b * XSTR + 32 + k] =
                __float2half_rn(ENC[((size_t)(b0g + b) * TT + eidx) * EE + k]);
        }
        // GY partials (warps 8-15): 2 kt x 2 mtiles each
        if (wid >= 8) {
            float Ym[8] = {0,0,0,0,0,0,0,0};
            const __half* hr = H1B + g * HSTR;
            const int kbase = 2 * (wid - 8);
#pragma unroll
            for (int l = 0; l < 4; ++l) {
                const int kt = kbase + (l >> 1);
                uint4 ay = *(const uint4*)(gyp + l * 256);
                const u32 b0 = *(const u32*)(hr + kt * 16 + 2 * tq);
                const u32 b1 = *(const u32*)(hr + kt * 16 + 8 + 2 * tq);
                hmma(Ym + 4 * (l & 1), ay, b0, b1);
            }
            PY[(wid - 8) * 2 + 0][lane] = make_float4(Ym[0], Ym[1], Ym[2], Ym[3]);
            PY[(wid - 8) * 2 + 1][lane] = make_float4(Ym[4], Ym[5], Ym[6], Ym[7]);
            asm volatile("bar.arrive 7, 320;" ::: "memory");
        }
        // GY reduce + y/x write (warps 0,1)
        if (wid < 2) {
            asm volatile("bar.sync 7, 320;" ::: "memory");
            float Y0 = 0.f, Y1 = 0.f, Y2 = 0.f, Y3 = 0.f;
#pragma unroll
            for (int w = 0; w < 8; ++w) {
                const float4 v = PY[w * 2 + wid][lane];
                Y0 += v.x; Y1 += v.y; Y2 += v.z; Y3 += v.w;
            }
            float Y[4] = {Y0, Y1, Y2, Y3};
#pragma unroll
            for (int p = 0; p < 4; ++p) {
                const bool a = (p < 2);
                const int i = 16 * wid + g + (a ? 0 : 8);
                const int b = 2 * tq + (p & 1);
                const float y = Y[p] + (a ? bya : byb);
                outseq[((size_t)(b0g + b) * TM1 + t) * II + i] = y;
                const bool keep = ((p & 1) ? kp1 : kp0) != 0;
                XB[b * XSTR + i] = __float2half_rn(keep ? xpre[p] : y);
            }
        }

        // ---- G0h(t+1): Whh0 x h0(t), 16kt (carry into Cr,Cz,Ch) ----
#pragma unroll
        for (int p = 0; p < 4; ++p) { Cr[p] = 0.f; Cz[p] = 0.f; Ch[p] = 0.f; }
        {
            const __half* hb = XB + g * XSTR + 64 + bi * 256;
            {
                const u32 b0 = *(const u32*)(hb + 2 * tq);
                const u32 b1 = *(const u32*)(hb + 8 + 2 * tq);
                hmma(Cr, pg0, b0, b1); hmma(Cz, pg1, b0, b1); hmma(Ch, pg2, b0, b1);
            }
#pragma unroll 4
            for (int kt = 1; kt < 16; ++kt) {
                const u32 b0 = *(const u32*)(hb + kt * 16 + 2 * tq);
                const u32 b1 = *(const u32*)(hb + kt * 16 + 8 + 2 * tq);
                uint4 ar = *(const uint4*)tp; tp += 256;
                uint4 az = *(const uint4*)tp; tp += 256;
                uint4 ah = *(const uint4*)tp; tp += 256;
                hmma(Cr, ar, b0, b1); hmma(Cz, az, b0, b1); hmma(Ch, ah, b0, b1);
            }
        }
        // ---- GB(t+1): Whh1 x h1(t), 16kt (carry into Dr,Dz,Dh) ----
#pragma unroll
        for (int p = 0; p < 4; ++p) { Dr[p] = 0.f; Dz[p] = 0.f; Dh[p] = 0.f; }
        {
            const __half* hr = H1B + g * HSTR;
#pragma unroll 4
            for (int kt = 0; kt < 16; ++kt) {
                const u32 b0 = *(const u32*)(hr + kt * 16 + 2 * tq);
                const u32 b1 = *(const u32*)(hr + kt * 16 + 8 + 2 * tq);
                uint4 ar = *(const uint4*)tp; tp += 256;
                uint4 az = *(const uint4*)tp; tp += 256;
                uint4 ah = *(const uint4*)tp; tp += 256;
                hmma(Dr, ar, b0, b1); hmma(Dz, az, b0, b1); hmma(Dh, ah, b0, b1);
            }
        }

        // prefetch next head kt0
        pg0 = *(const uint4*)(tpw);
        pg1 = *(const uint4*)(tpw + 256);
        pg2 = *(const uint4*)(tpw + 512);
        __syncthreads();   // BAR-C: x(t+1)/enc published
    }

    if (write_h1) {
#pragma unroll
        for (int p = 0; p < 4; ++p) {
            const int b = b0g + 2 * tq + (p & 1);
            const int u = (p < 2) ? u1 : u2;
            outh1[(size_t)b * HH + u] = h1[p];
        }
    }
}

extern "C" void kernel_launch(void* const* d_in, const int* in_sizes, int n_in,
                              void* d_out, int out_size) {
    const float* X    = (const float*)d_in[0];
    const float* ENC  = (const float*)d_in[1];
    const int*   MASK = (const int*)d_in[2];
    const float* wih0 = (const float*)d_in[3];
    const float* whh0 = (const float*)d_in[4];
    const float* bih0 = (const float*)d_in[5];
    const float* bhh0 = (const float*)d_in[6];
    const float* wih1 = (const float*)d_in[7];
    const float* whh1 = (const float*)d_in[8];
    const float* bih1 = (const float*)d_in[9];
    const float* bhh1 = (const float*)d_in[10];
    const float* wout = (const float*)d_in[11];
    const float* bout = (const float*)d_in[12];

    float* outseq = (float*)d_out;
    const int seqsz = BB * TM1 * II;
    float* outh1  = outseq + seqsz;
    const int write_h1 = (out_size >= seqsz + BB * HH) ? 1 : 0;

    prep_kernel<<<(NTILE_TOT * 256 + 255) / 256, 256>>>(wih0, whh0, wih1, whh1, wout);

    arrnn_kernel<<<NCTA, NTH>>>(X, ENC, MASK,
                                bih0, bhh0, bih1, bhh1, bout,
                                outseq, outh1, write_h1);
}

// round 14
// speedup vs baseline: 1.5262x; 1.0017x over previous
#include <cuda_runtime.h>
#include <cuda_fp16.h>
#include <cstdint>

typedef unsigned int u32;

#define BB   512
#define TT   1024
#define TM1  1023
#define II   32
#define EE   32
#define HH   256
#define KIN  64

#define NCTA 64
#define BPB  8
#define NTH  512     // 16 warps

// per-warp streams: warps 0-7: 156 tiles; warps 8-15: 160 (incl. 4 GY tiles)
#define NTILE_TOT (8*156 + 8*160)   // 2528

// XB row: [x(64) | h0_buf0(256) | h0_buf1(256)] pad-> 584 halfs
#define XSTR 584
#define HSTR 264

__device__ __align__(1024) __half SCHED[NTILE_TOT * 256];

// ---- prep: consumption order = head(x-part 12) | GC(48) | G0h(48) | GB(48) | [GY(4) w>=8]
__global__ void prep_kernel(const float* __restrict__ wih0, const float* __restrict__ whh0,
                            const float* __restrict__ wih1, const float* __restrict__ whh1,
                            const float* __restrict__ wout)
{
    int idx = blockIdx.x * blockDim.x + threadIdx.x;
    if (idx >= NTILE_TOT * 256) return;
    const int j    = idx & 7;
    const int lane = (idx >> 3) & 31;
    const int tile = idx >> 8;

    int w, r;
    if (tile < 8 * 156) { w = tile / 156; r = tile % 156; }
    else { int t2 = tile - 8 * 156; w = 8 + t2 / 160; r = t2 % 160; }

    const int tq = lane & 3;
    const int il = (lane >> 2) + 8 * ((j >> 1) & 1);
    const int kl = tq * 2 + (j & 1) + 8 * (j >> 2);

    float v;
    if (r < 12) {              // head: W_ih0 x-part, kt0-3 {r,z,i}
        const int kt = r / 3, kind = r % 3;
        v = wih0[(kind * 256 + 16 * w + il) * KIN + kt * 16 + kl];
    } else if (r < 60) {       // GC: W_ih1 {r,z,i}
        const int rr = r - 12, kt = rr / 3, kind = rr % 3;
        v = wih1[(kind * 256 + 16 * w + il) * HH + kt * 16 + kl];
    } else if (r < 108) {      // G0h: W_hh0 {r,z,h}
        const int rr = r - 60, kt = rr / 3, kind = rr % 3;
        v = whh0[(kind * 256 + 16 * w + il) * HH + kt * 16 + kl];
    } else if (r < 156) {      // GB: W_hh1 {r,z,h}
        const int rr = r - 108, kt = rr / 3, kind = rr % 3;
        v = whh1[(kind * 256 + 16 * w + il) * HH + kt * 16 + kl];
    } else {                   // GY (warps 8-15): kt = 2*(w-8)+(local>>1), mtile = local&1
        const int local = r - 156;
        const int kt = 2 * (w - 8) + (local >> 1);
        const int mt = local & 1;
        v = wout[(16 * mt + il) * HH + kt * 16 + kl];
    }
    SCHED[tile * 256 + lane * 8 + j] = __float2half_rn(v);
}

__device__ __forceinline__ float tanha(float x) {
    float y; asm("tanh.approx.f32 %0, %1;" : "=f"(y) : "f"(x)); return y;
}
__device__ __forceinline__ float siga(float x) {
    return fmaf(tanha(0.5f * x), 0.5f, 0.5f);
}
__device__ __forceinline__ void hmma(float* c, uint4 a, u32 b0, u32 b1) {
    asm volatile("mma.sync.aligned.m16n8k16.row.col.f32.f16.f16.f32 "
                 "{%0,%1,%2,%3}, {%4,%5,%6,%7}, {%8,%9}, {%0,%1,%2,%3};"
                 : "+f"(c[0]), "+f"(c[1]), "+f"(c[2]), "+f"(c[3])
                 : "r"(a.x), "r"(a.y), "r"(a.z), "r"(a.w), "r"(b0), "r"(b1));
}

// L1-pinned load: these lines survive the per-step streaming (re-read 1023x)
__device__ __forceinline__ uint4 ldg_pin(const __half* p) {
    uint4 v;
    asm("ld.global.nc.L1::evict_last.v4.u32 {%0,%1,%2,%3}, [%4];"
        : "=r"(v.x), "=r"(v.y), "=r"(v.z), "=r"(v.w) : "l"(p));
    return v;
}
// streaming load: do not displace pinned lines
__device__ __forceinline__ uint4 ldg_stream(const __half* p) {
    uint4 v;
    asm("ld.global.nc.L1::evict_first.v4.u32 {%0,%1,%2,%3}, [%4];"
        : "=r"(v.x), "=r"(v.y), "=r"(v.z), "=r"(v.w) : "l"(p));
    return v;
}

__global__ void __launch_bounds__(NTH, 1)
arrnn_kernel(const float* __restrict__ X,
             const float* __restrict__ ENC,
             const int*   __restrict__ MASK,
             const float* __restrict__ bih0, const float* __restrict__ bhh0,
             const float* __restrict__ bih1, const float* __restrict__ bhh1,
             const float* __restrict__ bout,
             float* __restrict__ outseq, float* __restrict__ outh1,
             int write_h1)
{
    __shared__ __align__(16) __half XB[BPB * XSTR];
    __shared__ __align__(16) __half H1B[BPB * HSTR];
    __shared__ __align__(16) float  bsm[8 * 256];
    __shared__ __align__(16) float4 PY[16][32];    // GY partials [w8*2+mtile][lane]

    const int tid  = threadIdx.x;
    const int wid  = tid >> 5;
    const int lane = tid & 31;
    const int g    = lane >> 2;
    const int tq   = lane & 3;
    const int b0g  = blockIdx.x * BPB;

    const int u1 = 16 * wid + g;
    const int u2 = u1 + 8;

    for (int i = tid; i < 8 * 256; i += NTH) {
        const int k = i >> 8, u = i & 255;
        float v;
        switch (k) {
            case 0: v = bih0[u] + bhh0[u]; break;
            case 1: v = bih0[256 + u] + bhh0[256 + u]; break;
            case 2: v = bih0[512 + u]; break;
            case 3: v = bhh0[512 + u]; break;
            case 4: v = bih1[u] + bhh1[u]; break;
            case 5: v = bih1[256 + u] + bhh1[256 + u]; break;
            case 6: v = bih1[512 + u]; break;
            default: v = bhh1[512 + u]; break;
        }
        bsm[i] = v;
    }
    const float bya = (wid < 2) ? bout[16 * wid + g] : 0.0f;
    const float byb = (wid < 2) ? bout[16 * wid + g + 8] : 0.0f;

    float h0[4] = {0.f, 0.f, 0.f, 0.f};
    float h1[4] = {0.f, 0.f, 0.f, 0.f};

    // carry accumulators (h-parts of next step), zero = correct for t=0
    float Cr[4] = {0,0,0,0}, Cz[4] = {0,0,0,0}, Ch[4] = {0,0,0,0};
    float Dr[4] = {0,0,0,0}, Dz[4] = {0,0,0,0}, Dh[4] = {0,0,0,0};

    // init XB / H1B, build x(0)|enc(1)
    for (int i = tid; i < BPB * 512; i += NTH)
        XB[(i >> 9) * XSTR + 64 + (i & 511)] = __float2half_rn(0.f);
    for (int i = tid; i < BPB * HSTR; i += NTH) H1B[i] = __float2half_rn(0.f);
    for (int i = tid; i < BPB * KIN; i += NTH) {
        const int b = i >> 6, k = i & 63;
        const int gb = b0g + b;
        const float v = (k < II) ? X[((size_t)gb * TT) * II + k]
                                 : ENC[((size_t)gb * TT + 1) * EE + (k - II)];
        XB[b * XSTR + k] = __float2half_rn(v);
    }
    __syncthreads();

    const int base_t = (wid < 8) ? wid * 156 : 8 * 156 + (wid - 8) * 160;
    const __half* tpw = SCHED + (size_t)base_t * 256 + lane * 8;
    const __half* gyp = tpw + 156 * 256;     // valid for wid>=8 only

    // prefetch head kt0 (tiles 0-2, pinned)
    uint4 pg0 = ldg_pin(tpw);
    uint4 pg1 = ldg_pin(tpw + 256);
    uint4 pg2 = ldg_pin(tpw + 512);

    for (int t = 0; t < TM1; ++t) {
        const int bi = t & 1;                 // h0 buffer for this step
        const __half* xr = XB + g * XSTR;

        // ================= HEAD: x-part of G0 (kt0-3) =================
        float Ci[4] = {0.f,0.f,0.f,0.f};
        {
            const u32 b0 = *(const u32*)(xr + 2 * tq);
            const u32 b1 = *(const u32*)(xr + 8 + 2 * tq);
            hmma(Cr, pg0, b0, b1); hmma(Cz, pg1, b0, b1); hmma(Ci, pg2, b0, b1);
        }
        const __half* tp = tpw + 3 * 256;
#pragma unroll
        for (int kt = 1; kt < 4; ++kt) {      // tiles 3-11 (pinned)
            const u32 b0 = *(const u32*)(xr + kt * 16 + 2 * tq);
            const u32 b1 = *(const u32*)(xr + kt * 16 + 8 + 2 * tq);
            uint4 ar = ldg_pin(tp); tp += 256;
            uint4 az = ldg_pin(tp); tp += 256;
            uint4 ai = ldg_pin(tp); tp += 256;
            hmma(Cr, ar, b0, b1); hmma(Cz, az, b0, b1); hmma(Ci, ai, b0, b1);
        }
        // prefetch GC kt0 (tiles 12-14, pinned)
        uint4 pc0 = ldg_pin(tp);
        uint4 pc1 = ldg_pin(tp + 256);
        uint4 pc2 = ldg_pin(tp + 512);
        tp += 3 * 256;

        // ---- epi0: h0(t) -> XB buf bi ----
        {
            const float br_a = bsm[u1],       br_b = bsm[u2];
            const float bz_a = bsm[256 + u1], bz_b = bsm[256 + u2];
            const float bi_a = bsm[512 + u1], bi_b = bsm[512 + u2];
            const float bn_a = bsm[768 + u1], bn_b = bsm[768 + u2];
#pragma unroll
            for (int p = 0; p < 4; ++p) {
                const bool a = (p < 2);
                const float rr = siga(Cr[p] + (a ? br_a : br_b));
                const float zz = siga(Cz[p] + (a ? bz_a : bz_b));
                const float nn = tanha(Ci[p] + (a ? bi_a : bi_b) + rr * (Ch[p] + (a ? bn_a : bn_b)));
                h0[p] = (1.0f - zz) * nn + zz * h0[p];
                XB[(2 * tq + (p & 1)) * XSTR + 64 + bi * 256 + (a ? u1 : u2)]
                    = __float2half_rn(h0[p]);
            }
        }
        __syncthreads();   // BAR-A: h0(t) published

        // ================= GC: Wih1 x h0(t), 16kt =================
        float Di[4] = {0.f,0.f,0.f,0.f};
        {
            const __half* hb = XB + g * XSTR + 64 + bi * 256;
            {
                const u32 b0 = *(const u32*)(hb + 2 * tq);
                const u32 b1 = *(const u32*)(hb + 8 + 2 * tq);
                hmma(Dr, pc0, b0, b1); hmma(Dz, pc1, b0, b1); hmma(Di, pc2, b0, b1);
            }
#pragma unroll
            for (int kt = 1; kt < 3; ++kt) {   // tiles 15-20 (pinned)
                const u32 b0 = *(const u32*)(hb + kt * 16 + 2 * tq);
                const u32 b1 = *(const u32*)(hb + kt * 16 + 8 + 2 * tq);
                uint4 ar = ldg_pin(tp); tp += 256;
                uint4 az = ldg_pin(tp); tp += 256;
                uint4 ai = ldg_pin(tp); tp += 256;
                hmma(Dr, ar, b0, b1); hmma(Dz, az, b0, b1); hmma(Di, ai, b0, b1);
            }
#pragma unroll 4
            for (int kt = 3; kt < 16; ++kt) {  // tiles 21-59 (stream)
                const u32 b0 = *(const u32*)(hb + kt * 16 + 2 * tq);
                const u32 b1 = *(const u32*)(hb + kt * 16 + 8 + 2 * tq);
                uint4 ar = ldg_stream(tp); tp += 256;
                uint4 az = ldg_stream(tp); tp += 256;
                uint4 ai = ldg_stream(tp); tp += 256;
                hmma(Dr, ar, b0, b1); hmma(Dz, az, b0, b1); hmma(Di, ai, b0, b1);
            }
        }

        // ---- epi1: h1(t) -> H1B ----
        {
            const float br_a = bsm[1024 + u1], br_b = bsm[1024 + u2];
            const float bz_a = bsm[1280 + u1], bz_b = bsm[1280 + u2];
            const float bi_a = bsm[1536 + u1], bi_b = bsm[1536 + u2];
            const float bn_a = bsm[1792 + u1], bn_b = bsm[1792 + u2];
#pragma unroll
            for (int p = 0; p < 4; ++p) {
                const bool a = (p < 2);
                const float rr = siga(Dr[p] + (a ? br_a : br_b));
                const float zz = siga(Dz[p] + (a ? bz_a : bz_b));
                const float nn = tanha(Di[p] + (a ? bi_a : bi_b) + rr * (Dh[p] + (a ? bn_a : bn_b)));
                h1[p] = (1.0f - zz) * nn + zz * h1[p];
                H1B[(2 * tq + (p & 1)) * HSTR + (a ? u1 : u2)] = __float2half_rn(h1[p]);
            }
        }

        // prefetch tail kt0 (tiles 60-62, stream) + warps 0,1: next-step mask/X
        pg0 = ldg_stream(tpw + 60 * 256);
        pg1 = ldg_stream(tpw + 61 * 256);
        pg2 = ldg_stream(tpw + 62 * 256);
        tp += 3 * 256;     // skip prefetched tiles 60-62 in the stream
        int kp0 = 0, kp1 = 0;
        float xpre[4];
        if (wid < 2) {
            kp0 = MASK[(b0g + 2 * tq) * TT + (t + 1)];
            kp1 = MASK[(b0g + 2 * tq + 1) * TT + (t + 1)];
#pragma unroll
            for (int p = 0; p < 4; ++p) {
                const int i = 16 * wid + g + ((p < 2) ? 0 : 8);
                const int b = 2 * tq + (p & 1);
                xpre[p] = X[((size_t)(b0g + b) * TT + (t + 1)) * II + i];
            }
        }
        __syncthreads();   // BAR-B: h1(t) published

        // ================= TAIL =================
        // enc(t+2) for the next head (warps 2-9)
        if (wid >= 2 && wid < 10) {
            const int i2 = tid - 64;
            const int b = i2 >> 5, k = i2 & 31;
            const int eidx = (t + 2 < TT) ? (t + 2) : (TT - 1);
            XB[b * XSTR + 32 + k] =
                __float2half_rn(ENC[((size_t)(b0g + b) * TT + eidx) * EE + k]);
        }
        // GY partials (warps 8-15): 2 kt x 2 mtiles each
        if (wid >= 8) {
            float Ym[8] = {0,0,0,0,0,0,0,0};
            const __half* hr = H1B + g * HSTR;
            const int kbase = 2 * (wid - 8);
#pragma unroll
            for (int l = 0; l < 4; ++l) {
                const int kt = kbase + (l >> 1);
                uint4 ay = ldg_stream(gyp + l * 256);
                const u32 b0 = *(const u32*)(hr + kt * 16 + 2 * tq);
                const u32 b1 = *(const u32*)(hr + kt * 16 + 8 + 2 * tq);
                hmma(Ym + 4 * (l & 1), ay, b0, b1);
            }
            PY[(wid - 8) * 2 + 0][lane] = make_float4(Ym[0], Ym[1], Ym[2], Ym[3]);
            PY[(wid - 8) * 2 + 1][lane] = make_float4(Ym[4], Ym[5], Ym[6], Ym[7]);
            asm volatile("bar.arrive 7, 320;" ::: "memory");
        }
        // GY reduce + y/x write (warps 0,1)
        if (wid < 2) {
            asm volatile("bar.sync 7, 320;" ::: "memory");
            float Y0 = 0.f, Y1 = 0.f, Y2 = 0.f, Y3 = 0.f;
#pragma unroll
            for (int w = 0; w < 8; ++w) {
                const float4 v = PY[w * 2 + wid][lane];
                Y0 += v.x; Y1 += v.y; Y2 += v.z; Y3 += v.w;
            }
            float Y[4] = {Y0, Y1, Y2, Y3};
#pragma unroll
            for (int p = 0; p < 4; ++p) {
                const bool a = (p < 2);
                const int i = 16 * wid + g + (a ? 0 : 8);
                const int b = 2 * tq + (p & 1);
                const float y = Y[p] + (a ? bya : byb);
                outseq[((size_t)(b0g + b) * TM1 + t) * II + i] = y;
                const bool keep = ((p & 1) ? kp1 : kp0) != 0;
                XB[b * XSTR + i] = __float2half_rn(keep ? xpre[p] : y);
            }
        }

        // ---- G0h(t+1): Whh0 x h0(t), 16kt (carry into Cr,Cz,Ch) ----
#pragma unroll
        for (int p = 0; p < 4; ++p) { Cr[p] = 0.f; Cz[p] = 0.f; Ch[p] = 0.f; }
        {
            const __half* hb = XB + g * XSTR + 64 + bi * 256;
            {
                const u32 b0 = *(const u32*)(hb + 2 * tq);
                const u32 b1 = *(const u32*)(hb + 8 + 2 * tq);
                hmma(Cr, pg0, b0, b1); hmma(Cz, pg1, b0, b1); hmma(Ch, pg2, b0, b1);
            }
#pragma unroll 4
            for (int kt = 1; kt < 16; ++kt) {
                const u32 b0 = *(const u32*)(hb + kt * 16 + 2 * tq);
                const u32 b1 = *(const u32*)(hb + kt * 16 + 8 + 2 * tq);
                uint4 ar = ldg_stream(tp); tp += 256;
                uint4 az = ldg_stream(tp); tp += 256;
                uint4 ah = ldg_stream(tp); tp += 256;
                hmma(Cr, ar, b0, b1); hmma(Cz, az, b0, b1); hmma(Ch, ah, b0, b1);
            }
        }
        // ---- GB(t+1): Whh1 x h1(t), 16kt (carry into Dr,Dz,Dh) ----
#pragma unroll
        for (int p = 0; p < 4; ++p) { Dr[p] = 0.f; Dz[p] = 0.f; Dh[p] = 0.f; }
        {
            const __half* hr = H1B + g * HSTR;
#pragma unroll 4
            for (int kt = 0; kt < 16; ++kt) {
                const u32 b0 = *(const u32*)(hr + kt * 16 + 2 * tq);
                const u32 b1 = *(const u32*)(hr + kt * 16 + 8 + 2 * tq);
                uint4 ar = ldg_stream(tp); tp += 256;
                uint4 az = ldg_stream(tp); tp += 256;
                uint4 ah = ldg_stream(tp); tp += 256;
                hmma(Dr, ar, b0, b1); hmma(Dz, az, b0, b1); hmma(Dh, ah, b0, b1);
            }
        }

        // prefetch next head kt0 (pinned -> L1 hit after step 0)
        pg0 = ldg_pin(tpw);
        pg1 = ldg_pin(tpw + 256);
        pg2 = ldg_pin(tpw + 512);
        __syncthreads();   // BAR-C: x(t+1)/enc published
    }

    if (write_h1) {
#pragma unroll
        for (int p = 0; p < 4; ++p) {
            const int b = b0g + 2 * tq + (p & 1);
            const int u = (p < 2) ? u1 : u2;
            outh1[(size_t)b * HH + u] = h1[p];
        }
    }
}

extern "C" void kernel_launch(void* const* d_in, const int* in_sizes, int n_in,
                              void* d_out, int out_size) {
    const float* X    = (const float*)d_in[0];
    const float* ENC  = (const float*)d_in[1];
    const int*   MASK = (const int*)d_in[2];
    const float* wih0 = (const float*)d_in[3];
    const float* whh0 = (const float*)d_in[4];
    const float* bih0 = (const float*)d_in[5];
    const float* bhh0 = (const float*)d_in[6];
    const float* wih1 = (const float*)d_in[7];
    const float* whh1 = (const float*)d_in[8];
    const float* bih1 = (const float*)d_in[9];
    const float* bhh1 = (const float*)d_in[10];
    const float* wout = (const float*)d_in[11];
    const float* bout = (const float*)d_in[12];

    float* outseq = (float*)d_out;
    const int seqsz = BB * TM1 * II;
    float* outh1  = outseq + seqsz;
    const int write_h1 = (out_size >= seqsz + BB * HH) ? 1 : 0;

    prep_kernel<<<(NTILE_TOT * 256 + 255) / 256, 256>>>(wih0, whh0, wih1, whh1, wout);

    arrnn_kernel<<<NCTA, NTH>>>(X, ENC, MASK,
                                bih0, bhh0, bih1, bhh1, bout,
                                outseq, outh1, write_h1);
}